// round 16
// baseline (speedup 1.0000x reference)
#include <cuda_runtime.h>
#include <cuda_fp16.h>
#include <cstdint>

// ---------------------------------------------------------------------------
// LinkPredModel: 2-layer GraphSAGE (mean agg) + edge dot
// R16: champion base + GEMM B-fragments staged in SMEM (32KB tile/phase,
//      cooperative load) — removes 4x-redundant per-warp weight LDGs that
//      were the GEMM's LSU bottleneck. Stream fork dropped (neutral).
//      k_agg PERMANENTLY FROZEN (5 modification attempts all regressed).
// ---------------------------------------------------------------------------

#define MAXN 100000
#define MAXE 3200000

__device__ int   g_cnt[MAXN];
__device__ int   g_rowptr[MAXN + 1];
__device__ int   g_cursor[MAXN];
__device__ float g_dinv[MAXN];
__device__ int   g_col[MAXE];
__device__ int   g_is64;
__device__ int   g_bsum[64];
__device__ int   g_boff[64];
__device__ int   g_arrive;

__device__ __align__(16) __half g_xh  [(long long)MAXN * 128];
__device__ __align__(16) __half g_aggh[(long long)MAXN * 128];
__device__ __align__(16) __half g_h1h [(long long)MAXN * 128];
__device__ __align__(16) __half g_h2h [(long long)MAXN * 128];
// fragment-packed tf32 weights: [W1l, W1r, W2l, W2r] x 16384 u32 each
__device__ __align__(16) uint32_t g_wtf[4 * 16384];

// ---- index accessor: tolerate int64 or int32 edge index buffers ----------
__device__ __forceinline__ int eidx(const void* p, long long i, int is64) {
    if (is64) return (int)__ldg(((const long long*)p) + i);
    return __ldg(((const int*)p) + i);
}

__device__ __forceinline__ uint32_t f2tf32(float f) {
    uint32_t u;
    asm("cvt.rna.tf32.f32 %0, %1;" : "=r"(u) : "f"(f));
    return u;
}

#define MMA_TF32(d, a, b) \
    asm volatile("mma.sync.aligned.m16n8k8.row.col.f32.tf32.tf32.f32 " \
        "{%0,%1,%2,%3},{%4,%5,%6,%7},{%8,%9},{%0,%1,%2,%3};" \
        : "+f"((d)[0]), "+f"((d)[1]), "+f"((d)[2]), "+f"((d)[3]) \
        : "r"((a).x), "r"((a).y), "r"((a).z), "r"((a).w), \
          "r"((uint32_t)((b) & 0xFFFFFFFFull)), "r"((uint32_t)((b) >> 32)))

// -------------------------- CSR build --------------------------------------
__global__ void k_init(const void* ei, int slots64, int N) {
    int i = blockIdx.x * blockDim.x + threadIdx.x;
    if (i < N) g_cnt[i] = 0;
    if (i == 0) g_arrive = 0;
    if (blockIdx.x == 0) {
        __shared__ int nonzero;
        if (threadIdx.x == 0) nonzero = 0;
        __syncthreads();
        const int* w = (const int*)ei;
        int slots = slots64 < 4096 ? slots64 : 4096;
        int any = 0;
        for (int t = threadIdx.x; t < slots; t += blockDim.x)
            if (w[2 * t + 1] != 0) any = 1;
        if (any) atomicOr(&nonzero, 1);
        __syncthreads();
        if (threadIdx.x == 0) g_is64 = (nonzero == 0) ? 1 : 0;
    }
}

// 2 edges per thread; vector index loads when E is even (uniform branch).
__global__ void k_count(const void* ei, int E) {
    int i = blockIdx.x * blockDim.x + threadIdx.x;
    int is64 = g_is64;
    if ((E & 1) == 0) {
        int e0 = i * 2;
        if (e0 >= E) return;
        int d0, d1;
        if (is64) {
            longlong2 dd = __ldg((const longlong2*)ei + (E + e0) / 2);
            d0 = (int)dd.x; d1 = (int)dd.y;
        } else {
            int2 dd = __ldg((const int2*)ei + (E + e0) / 2);
            d0 = dd.x; d1 = dd.y;
        }
        atomicAdd(&g_cnt[d0], 1);
        atomicAdd(&g_cnt[d1], 1);
    } else {
        if (i >= E) return;
        int d = eidx(ei, (long long)E + i, is64);
        atomicAdd(&g_cnt[d], 1);
    }
}

// scan1 + fused top-level scan (last-block-done).
__global__ void k_scan1(int nb, int N) {
    __shared__ int s[256];
    __shared__ int amLast;
    int b = blockIdx.x, t = threadIdx.x;
    int base = b * 2048 + t * 8;
    int v[8];
    int sum = 0;
#pragma unroll
    for (int j = 0; j < 8; j++) {
        int i = base + j;
        v[j] = (i < N) ? g_cnt[i] : 0;
        sum += v[j];
    }
    s[t] = sum;
    __syncthreads();
    for (int off = 1; off < 256; off <<= 1) {
        int x = (t >= off) ? s[t - off] : 0;
        __syncthreads();
        s[t] += x;
        __syncthreads();
    }
    int ex = s[t] - sum;
#pragma unroll
    for (int j = 0; j < 8; j++) {
        int i = base + j;
        if (i < N) g_rowptr[i] = ex;
        ex += v[j];
    }
    if (t == 255) g_bsum[b] = s[255];

    __threadfence();
    __syncthreads();
    if (t == 0) {
        int prev = atomicAdd(&g_arrive, 1);
        amLast = (prev == nb - 1);
    }
    __syncthreads();
    if (amLast) {
        __shared__ int s2[64];
        int vv = (t < nb) ? g_bsum[t] : 0;
        if (t < 64) s2[t] = vv;
        __syncthreads();
        for (int off = 1; off < 64; off <<= 1) {
            int x = (t < 64 && t >= off) ? s2[t - off] : 0;
            __syncthreads();
            if (t < 64) s2[t] += x;
            __syncthreads();
        }
        if (t < nb) g_boff[t] = s2[t] - vv;
        if (t == 63) g_rowptr[N] = s2[63];
    }
}

// ---- merged prep: [scan3 | weight tf32-pack | x fp32->fp16] ---------------
__global__ void k_prep(int N, int ba,
                       const float* __restrict__ W1l, const float* __restrict__ W1r,
                       const float* __restrict__ W2l, const float* __restrict__ W2r,
                       const float* __restrict__ x, __half* __restrict__ xh) {
    int tid = threadIdx.x;
    if (blockIdx.x < ba) {
        int i = blockIdx.x * 256 + tid;
        if (i < N) {
            int rp = g_rowptr[i] + g_boff[i >> 11];
            g_rowptr[i] = rp;
            g_cursor[i] = rp;
            int c = g_cnt[i];
            g_dinv[i] = 1.0f / (float)(c > 1 ? c : 1);
        }
    } else if (blockIdx.x < ba + 256) {
        int i = (blockIdx.x - ba) * 256 + tid;     // 0..65535
        int m = i >> 14, e = i & 16383;
        int k = e >> 7, c = e & 127;
        const float* Ws[4] = {W1l, W1r, W2l, W2r};
        uint32_t v = f2tf32(__ldg(Ws[m] + e));
        int p = k >> 6, s = (k >> 3) & 7, kk = k & 7;
        int nb = c >> 3;
        int lane = ((c & 7) << 2) | (kk & 3);
        int reg = kk >> 2;
        g_wtf[(((m * 2 + p) * 8 + s) * 16 + nb) * 64 + lane * 2 + reg] = v;
    } else {
        int i = (blockIdx.x - ba - 256) * 256 + tid;   // float4 index
        if (i < N * 32) {
            float4 v = __ldg((const float4*)x + i);
            __half2 h0 = __floats2half2_rn(v.x, v.y);
            __half2 h1 = __floats2half2_rn(v.z, v.w);
            uint2 ov;
            ov.x = *(uint32_t*)&h0;
            ov.y = *(uint32_t*)&h1;
            ((uint2*)xh)[i] = ov;
        }
    }
}

// 2 edges per thread; vector index loads when E is even (uniform branch).
__global__ void k_fill(const void* ei, int E) {
    int i = blockIdx.x * blockDim.x + threadIdx.x;
    int is64 = g_is64;
    if ((E & 1) == 0) {
        int e0 = i * 2;
        if (e0 >= E) return;
        int s0, s1, d0, d1;
        if (is64) {
            longlong2 ss = __ldg((const longlong2*)ei + e0 / 2);
            longlong2 dd = __ldg((const longlong2*)ei + (E + e0) / 2);
            s0 = (int)ss.x; s1 = (int)ss.y;
            d0 = (int)dd.x; d1 = (int)dd.y;
        } else {
            int2 ss = __ldg((const int2*)ei + e0 / 2);
            int2 dd = __ldg((const int2*)ei + (E + e0) / 2);
            s0 = ss.x; s1 = ss.y;
            d0 = dd.x; d1 = dd.y;
        }
        int p0 = atomicAdd(&g_cursor[d0], 1);
        g_col[p0] = s0;
        int p1 = atomicAdd(&g_cursor[d1], 1);
        g_col[p1] = s1;
    } else {
        if (i >= E) return;
        int src = eidx(ei, i, is64);
        int dst = eidx(ei, (long long)E + i, is64);
        int pos = atomicAdd(&g_cursor[dst], 1);
        g_col[pos] = src;
    }
}

// ------------- mean aggregation (fp16 gather, fp32 accumulate) -------------
// PERMANENTLY FROZEN R5/R8 structure — DO NOT MODIFY (5 attempts regressed).
__global__ void k_agg(const __half* __restrict__ hin, __half* __restrict__ out, int N) {
    int node = (blockIdx.x * blockDim.x + threadIdx.x) >> 5;
    int lane = threadIdx.x & 31;
    if (node >= N) return;
    int beg = g_rowptr[node];
    int end = g_rowptr[node + 1];
    const uint2* hp = (const uint2*)hin;   // 32 uint2 per row
    float a0 = 0.f, a1 = 0.f, a2 = 0.f, a3 = 0.f;
    float b0 = 0.f, b1 = 0.f, b2 = 0.f, b3 = 0.f;
    int j = beg;
    for (; j + 3 < end; j += 4) {
        int s0 = __ldg(&g_col[j]);
        int s1 = __ldg(&g_col[j + 1]);
        int s2 = __ldg(&g_col[j + 2]);
        int s3 = __ldg(&g_col[j + 3]);
        uint2 u0 = __ldg(&hp[(long long)s0 * 32 + lane]);
        uint2 u1 = __ldg(&hp[(long long)s1 * 32 + lane]);
        uint2 u2 = __ldg(&hp[(long long)s2 * 32 + lane]);
        uint2 u3 = __ldg(&hp[(long long)s3 * 32 + lane]);
        float2 p0 = __half22float2(*(__half2*)&u0.x);
        float2 p1 = __half22float2(*(__half2*)&u0.y);
        float2 q0 = __half22float2(*(__half2*)&u1.x);
        float2 q1 = __half22float2(*(__half2*)&u1.y);
        float2 r0 = __half22float2(*(__half2*)&u2.x);
        float2 r1 = __half22float2(*(__half2*)&u2.y);
        float2 t0 = __half22float2(*(__half2*)&u3.x);
        float2 t1 = __half22float2(*(__half2*)&u3.y);
        a0 += p0.x + r0.x; a1 += p0.y + r0.y; a2 += p1.x + r1.x; a3 += p1.y + r1.y;
        b0 += q0.x + t0.x; b1 += q0.y + t0.y; b2 += q1.x + t1.x; b3 += q1.y + t1.y;
    }
    for (; j < end; j++) {
        int s = __ldg(&g_col[j]);
        uint2 u = __ldg(&hp[(long long)s * 32 + lane]);
        float2 p0 = __half22float2(*(__half2*)&u.x);
        float2 p1 = __half22float2(*(__half2*)&u.y);
        a0 += p0.x; a1 += p0.y; a2 += p1.x; a3 += p1.y;
    }
    float dv = g_dinv[node];
    float m0 = (a0 + b0) * dv, m1 = (a1 + b1) * dv;
    float m2 = (a2 + b2) * dv, m3 = (a3 + b3) * dv;
    __half2 o01 = __floats2half2_rn(m0, m1);
    __half2 o23 = __floats2half2_rn(m2, m3);
    uint2 ov;
    ov.x = *(uint32_t*)&o01;
    ov.y = *(uint32_t*)&o23;
    ((uint2*)out)[(long long)node * 32 + lane] = ov;
}

// ------------------- tf32 tensor-core fused SAGE GEMM ----------------------
// B-fragments now staged in SMEM per K-phase (32KB tile, cooperative load):
// removes the 4x-duplicated per-warp weight LDGs (warp_m 0..3 share frags).
// Dynamic smem: sA 32KB + sB 32KB = 64KB; 2 CTA/SM = 128KB (fits 228KB).
__global__ void __launch_bounds__(256, 2)
k_gemm(const __half* __restrict__ A, const __half* __restrict__ X,
       const unsigned long long* __restrict__ wA,
       const unsigned long long* __restrict__ wX,
       const float* __restrict__ bias,
       __half* __restrict__ outH, int N, int leaky) {
    extern __shared__ char smem[];
    uint32_t* sA = (uint32_t*)smem;                          // 8192 u32 = 32KB
    unsigned long long* sB = (unsigned long long*)(smem + 32768);  // 4096 u64 = 32KB
    int tid = threadIdx.x;
    int lane = tid & 31;
    int wid = tid >> 5;
    int warp_n = wid & 1;
    int warp_m = wid >> 1;
    long long row0 = (long long)blockIdx.x * 128;

    float acc[2][8][4];
#pragma unroll
    for (int mi = 0; mi < 2; mi++)
#pragma unroll
        for (int ni = 0; ni < 8; ni++)
#pragma unroll
            for (int r = 0; r < 4; r++) acc[mi][ni][r] = 0.f;

#pragma unroll 1
    for (int seg = 0; seg < 2; seg++) {
        const __half* src = seg ? X : A;
        const unsigned long long* gw = seg ? wX : wA;
#pragma unroll 1
        for (int p = 0; p < 2; p++) {
            __syncthreads();
            // stage A tile (fragment order) — unchanged
#pragma unroll
            for (int it = 0; it < 8; it++) {
                int i = tid + it * 256;        // 2048 uint2 slots (4 halves)
                int r = i >> 4, kq = i & 15;
                long long grow = row0 + r;
                uint2 v = make_uint2(0, 0);
                if (grow < N)
                    v = __ldg((const uint2*)src + grow * 32 + p * 16 + kq);
                float2 f01 = __half22float2(*(__half2*)&v.x);
                float2 f23 = __half22float2(*(__half2*)&v.y);
                int k0 = kq * 4;
                int g = r & 15, mb = r >> 4;
                int sidx = k0 >> 3;
                int reg = ((g >> 3) & 1) | (((k0 & 7) >> 2) << 1);
                uint32_t base = (((sidx * 8 + mb) * 32 + ((g & 7) << 2)) << 2) + reg;
                sA[base]      = f2tf32(f01.x);
                sA[base + 4]  = f2tf32(f01.y);
                sA[base + 8]  = f2tf32(f23.x);
                sA[base + 12] = f2tf32(f23.y);
            }
            // stage B-fragment tile for this phase: 4096 u64 = 2048 uint4
            {
                const uint4* gw4 = (const uint4*)(gw + p * 4096);
                uint4* sB4 = (uint4*)sB;
#pragma unroll
                for (int it = 0; it < 8; it++)
                    sB4[tid + it * 256] = __ldg(gw4 + tid + it * 256);
            }
            __syncthreads();
#pragma unroll
            for (int s = 0; s < 8; s++) {
                uint4 a0 = *(const uint4*)&sA[((s * 8 + warp_m * 2 + 0) * 32 + lane) * 4];
                uint4 a1 = *(const uint4*)&sA[((s * 8 + warp_m * 2 + 1) * 32 + lane) * 4];
                unsigned long long bv[8];
#pragma unroll
                for (int nb = 0; nb < 8; nb++)
                    bv[nb] = sB[(s * 16 + warp_n * 8 + nb) * 32 + lane];
#pragma unroll
                for (int nb = 0; nb < 8; nb++) {
                    MMA_TF32(acc[0][nb], a0, bv[nb]);
                    MMA_TF32(acc[1][nb], a1, bv[nb]);
                }
            }
        }
    }

    int g4 = lane >> 2, t4 = lane & 3;
#pragma unroll
    for (int mi = 0; mi < 2; mi++) {
#pragma unroll
        for (int ni = 0; ni < 8; ni++) {
            int col = warp_n * 64 + ni * 8 + t4 * 2;
            float b0 = __ldg(bias + col);
            float b1 = __ldg(bias + col + 1);
            long long r0 = row0 + warp_m * 32 + mi * 16 + g4;
            float v0 = acc[mi][ni][0] + b0;
            float v1 = acc[mi][ni][1] + b1;
            float v2 = acc[mi][ni][2] + b0;
            float v3 = acc[mi][ni][3] + b1;
            if (leaky) {
                v0 = v0 >= 0.f ? v0 : 0.2f * v0;
                v1 = v1 >= 0.f ? v1 : 0.2f * v1;
                v2 = v2 >= 0.f ? v2 : 0.2f * v2;
                v3 = v3 >= 0.f ? v3 : 0.2f * v3;
            }
            if (r0 < N) {
                __half2 o = __floats2half2_rn(v0, v1);
                *(uint32_t*)(outH + r0 * 128 + col) = *(uint32_t*)&o;
            }
            if (r0 + 8 < N) {
                __half2 o = __floats2half2_rn(v2, v3);
                *(uint32_t*)(outH + (r0 + 8) * 128 + col) = *(uint32_t*)&o;
            }
        }
    }
}

// ------------------- link prediction dot (fp16 inputs) ----------------------
__global__ void k_dot(const __half* __restrict__ h, const void* __restrict__ eli,
                      float* __restrict__ out, int L) {
    int warp = (blockIdx.x * blockDim.x + threadIdx.x) >> 5;
    int lane = threadIdx.x & 31;
    if (warp >= L) return;
    int is64 = g_is64;
    int a = eidx(eli, warp, is64);
    int b = eidx(eli, (long long)L + warp, is64);
    const uint2* hp = (const uint2*)h;
    uint2 ua = __ldg(&hp[(long long)a * 32 + lane]);
    uint2 ub = __ldg(&hp[(long long)b * 32 + lane]);
    float2 a0 = __half22float2(*(__half2*)&ua.x);
    float2 a1 = __half22float2(*(__half2*)&ua.y);
    float2 b0 = __half22float2(*(__half2*)&ub.x);
    float2 b1 = __half22float2(*(__half2*)&ub.y);
    float s = a0.x * b0.x + a0.y * b0.y + a1.x * b1.x + a1.y * b1.y;
#pragma unroll
    for (int o = 16; o; o >>= 1) s += __shfl_xor_sync(0xFFFFFFFFu, s, o);
    if (lane == 0) out[warp] = s;
}

extern "C" void kernel_launch(void* const* d_in, const int* in_sizes, int n_in,
                              void* d_out, int out_size) {
    const float* x   = (const float*)d_in[0];
    const void*  ei  = d_in[1];
    const void*  eli = d_in[2];
    const float* W1l = (const float*)d_in[3];
    const float* b1  = (const float*)d_in[4];
    const float* W1r = (const float*)d_in[5];
    const float* W2l = (const float*)d_in[6];
    const float* b2  = (const float*)d_in[7];
    const float* W2r = (const float*)d_in[8];
    float* out = (float*)d_out;

    int N = in_sizes[0] / 128;
    int E = in_sizes[1] / 2;
    int L = in_sizes[2] / 2;

    __half *xh, *aggh, *h1h, *h2h;
    uint32_t* wtf;
    cudaGetSymbolAddress((void**)&xh,   g_xh);
    cudaGetSymbolAddress((void**)&aggh, g_aggh);
    cudaGetSymbolAddress((void**)&h1h,  g_h1h);
    cudaGetSymbolAddress((void**)&h2h,  g_h2h);
    cudaGetSymbolAddress((void**)&wtf,  g_wtf);

    cudaFuncSetAttribute(k_gemm, cudaFuncAttributeMaxDynamicSharedMemorySize, 65536);

    // CSR build + prep (scan2 fused into scan1 via last-block-done)
    k_init<<<(N + 255) / 256, 256>>>(ei, E, N);
    int cntThreads = (E & 1) ? E : E / 2;
    k_count<<<(cntThreads + 255) / 256, 256>>>(ei, E);
    int nb = (N + 2047) / 2048;
    k_scan1<<<nb, 256>>>(nb, N);
    int ba = (N + 255) / 256;
    int bc = (N * 32 + 255) / 256;
    k_prep<<<ba + 256 + bc, 256>>>(N, ba, W1l, W1r, W2l, W2r, x, xh);
    k_fill<<<(cntThreads + 255) / 256, 256>>>(ei, E);

    const unsigned long long* w1l = (const unsigned long long*)(wtf + 0 * 16384);
    const unsigned long long* w1r = (const unsigned long long*)(wtf + 1 * 16384);
    const unsigned long long* w2l = (const unsigned long long*)(wtf + 2 * 16384);
    const unsigned long long* w2r = (const unsigned long long*)(wtf + 3 * 16384);

    int aggBlocks = (N + 7) / 8;
    int gemmBlocks = (N + 127) / 128;

    // Layer 1
    k_agg<<<aggBlocks, 256>>>(xh, aggh, N);
    k_gemm<<<gemmBlocks, 256, 65536>>>(aggh, xh, w1l, w1r, b1, h1h, N, 1);
    // Layer 2
    k_agg<<<aggBlocks, 256>>>(h1h, aggh, N);
    k_gemm<<<gemmBlocks, 256, 65536>>>(aggh, h1h, w2l, w2r, b2, h2h, N, 0);
    // Edge dot
    k_dot<<<(L + 7) / 8, 256>>>(h2h, eli, out, L);
}

// round 17
// speedup vs baseline: 1.0505x; 1.0505x over previous
#include <cuda_runtime.h>
#include <cuda_fp16.h>
#include <cstdint>

// ---------------------------------------------------------------------------
// LinkPredModel: 2-layer GraphSAGE (mean agg) + edge dot
// R17: exact R12 champion (agg/gemm FROZEN) + two contained micro-opts:
//      k_dot 2-edges-per-warp (uint4 row loads), k_prep x-convert at
//      8 floats/thread. R16's GEMM smem staging reverted (regressed).
// ---------------------------------------------------------------------------

#define MAXN 100000
#define MAXE 3200000

__device__ int   g_cnt[MAXN];
__device__ int   g_rowptr[MAXN + 1];
__device__ int   g_cursor[MAXN];
__device__ float g_dinv[MAXN];
__device__ int   g_col[MAXE];
__device__ int   g_is64;
__device__ int   g_bsum[64];
__device__ int   g_boff[64];

__device__ __align__(16) __half g_xh  [(long long)MAXN * 128];
__device__ __align__(16) __half g_aggh[(long long)MAXN * 128];
__device__ __align__(16) __half g_h1h [(long long)MAXN * 128];
__device__ __align__(16) __half g_h2h [(long long)MAXN * 128];
// fragment-packed tf32 weights: [W1l, W1r, W2l, W2r] x 16384 u32 each
__device__ __align__(16) uint32_t g_wtf[4 * 16384];

// ---- index accessor: tolerate int64 or int32 edge index buffers ----------
__device__ __forceinline__ int eidx(const void* p, long long i, int is64) {
    if (is64) return (int)__ldg(((const long long*)p) + i);
    return __ldg(((const int*)p) + i);
}

__device__ __forceinline__ uint32_t f2tf32(float f) {
    uint32_t u;
    asm("cvt.rna.tf32.f32 %0, %1;" : "=r"(u) : "f"(f));
    return u;
}

#define MMA_TF32(d, a, b) \
    asm volatile("mma.sync.aligned.m16n8k8.row.col.f32.tf32.tf32.f32 " \
        "{%0,%1,%2,%3},{%4,%5,%6,%7},{%8,%9},{%0,%1,%2,%3};" \
        : "+f"((d)[0]), "+f"((d)[1]), "+f"((d)[2]), "+f"((d)[3]) \
        : "r"((a).x), "r"((a).y), "r"((a).z), "r"((a).w), \
          "r"((uint32_t)((b) & 0xFFFFFFFFull)), "r"((uint32_t)((b) >> 32)))

// -------------------------- CSR build --------------------------------------
__global__ void k_init(const void* ei, int slots64, int N) {
    int i = blockIdx.x * blockDim.x + threadIdx.x;
    if (i < N) g_cnt[i] = 0;
    if (blockIdx.x == 0) {
        __shared__ int nonzero;
        if (threadIdx.x == 0) nonzero = 0;
        __syncthreads();
        const int* w = (const int*)ei;
        int slots = slots64 < 4096 ? slots64 : 4096;
        int any = 0;
        for (int t = threadIdx.x; t < slots; t += blockDim.x)
            if (w[2 * t + 1] != 0) any = 1;
        if (any) atomicOr(&nonzero, 1);
        __syncthreads();
        if (threadIdx.x == 0) g_is64 = (nonzero == 0) ? 1 : 0;
    }
}

// 2 edges per thread; vector index loads when E is even (uniform branch).
__global__ void k_count(const void* ei, int E) {
    int i = blockIdx.x * blockDim.x + threadIdx.x;
    int is64 = g_is64;
    if ((E & 1) == 0) {
        int e0 = i * 2;
        if (e0 >= E) return;
        int d0, d1;
        if (is64) {
            longlong2 dd = __ldg((const longlong2*)ei + (E + e0) / 2);
            d0 = (int)dd.x; d1 = (int)dd.y;
        } else {
            int2 dd = __ldg((const int2*)ei + (E + e0) / 2);
            d0 = dd.x; d1 = dd.y;
        }
        atomicAdd(&g_cnt[d0], 1);
        atomicAdd(&g_cnt[d1], 1);
    } else {
        if (i >= E) return;
        int d = eidx(ei, (long long)E + i, is64);
        atomicAdd(&g_cnt[d], 1);
    }
}

__global__ void k_scan1(int N) {
    __shared__ int s[256];
    int b = blockIdx.x, t = threadIdx.x;
    int base = b * 2048 + t * 8;
    int v[8];
    int sum = 0;
#pragma unroll
    for (int j = 0; j < 8; j++) {
        int i = base + j;
        v[j] = (i < N) ? g_cnt[i] : 0;
        sum += v[j];
    }
    s[t] = sum;
    __syncthreads();
    for (int off = 1; off < 256; off <<= 1) {
        int x = (t >= off) ? s[t - off] : 0;
        __syncthreads();
        s[t] += x;
        __syncthreads();
    }
    int ex = s[t] - sum;
#pragma unroll
    for (int j = 0; j < 8; j++) {
        int i = base + j;
        if (i < N) g_rowptr[i] = ex;
        ex += v[j];
    }
    if (t == 255) g_bsum[b] = s[255];
}

__global__ void k_scan2(int nb, int N) {
    __shared__ int s[64];
    int t = threadIdx.x;
    int v = (t < nb) ? g_bsum[t] : 0;
    s[t] = v;
    __syncthreads();
    for (int off = 1; off < 64; off <<= 1) {
        int x = (t >= off) ? s[t - off] : 0;
        __syncthreads();
        s[t] += x;
        __syncthreads();
    }
    if (t < nb) g_boff[t] = s[t] - v;
    if (t == 63) g_rowptr[N] = s[63];
}

// ---- merged prep: [scan3 | weight tf32-pack | x fp32->fp16 (8/thread)] ----
__global__ void k_prep(int N, int ba,
                       const float* __restrict__ W1l, const float* __restrict__ W1r,
                       const float* __restrict__ W2l, const float* __restrict__ W2r,
                       const float* __restrict__ x, __half* __restrict__ xh) {
    int tid = threadIdx.x;
    if (blockIdx.x < ba) {
        int i = blockIdx.x * 256 + tid;
        if (i < N) {
            int rp = g_rowptr[i] + g_boff[i >> 11];
            g_rowptr[i] = rp;
            g_cursor[i] = rp;
            int c = g_cnt[i];
            g_dinv[i] = 1.0f / (float)(c > 1 ? c : 1);
        }
    } else if (blockIdx.x < ba + 256) {
        int i = (blockIdx.x - ba) * 256 + tid;     // 0..65535
        int m = i >> 14, e = i & 16383;
        int k = e >> 7, c = e & 127;
        const float* Ws[4] = {W1l, W1r, W2l, W2r};
        uint32_t v = f2tf32(__ldg(Ws[m] + e));
        int p = k >> 6, s = (k >> 3) & 7, kk = k & 7;
        int nb = c >> 3;
        int lane = ((c & 7) << 2) | (kk & 3);
        int reg = kk >> 2;
        g_wtf[(((m * 2 + p) * 8 + s) * 16 + nb) * 64 + lane * 2 + reg] = v;
    } else {
        int i = (blockIdx.x - ba - 256) * 256 + tid;   // 8-float group index
        if (i < N * 16) {
            float4 v0 = __ldg((const float4*)x + 2 * i);
            float4 v1 = __ldg((const float4*)x + 2 * i + 1);
            __half2 h0 = __floats2half2_rn(v0.x, v0.y);
            __half2 h1 = __floats2half2_rn(v0.z, v0.w);
            __half2 h2 = __floats2half2_rn(v1.x, v1.y);
            __half2 h3 = __floats2half2_rn(v1.z, v1.w);
            uint4 ov;
            ov.x = *(uint32_t*)&h0;
            ov.y = *(uint32_t*)&h1;
            ov.z = *(uint32_t*)&h2;
            ov.w = *(uint32_t*)&h3;
            ((uint4*)xh)[i] = ov;
        }
    }
}

// 2 edges per thread; vector index loads when E is even (uniform branch).
__global__ void k_fill(const void* ei, int E) {
    int i = blockIdx.x * blockDim.x + threadIdx.x;
    int is64 = g_is64;
    if ((E & 1) == 0) {
        int e0 = i * 2;
        if (e0 >= E) return;
        int s0, s1, d0, d1;
        if (is64) {
            longlong2 ss = __ldg((const longlong2*)ei + e0 / 2);
            longlong2 dd = __ldg((const longlong2*)ei + (E + e0) / 2);
            s0 = (int)ss.x; s1 = (int)ss.y;
            d0 = (int)dd.x; d1 = (int)dd.y;
        } else {
            int2 ss = __ldg((const int2*)ei + e0 / 2);
            int2 dd = __ldg((const int2*)ei + (E + e0) / 2);
            s0 = ss.x; s1 = ss.y;
            d0 = dd.x; d1 = dd.y;
        }
        int p0 = atomicAdd(&g_cursor[d0], 1);
        g_col[p0] = s0;
        int p1 = atomicAdd(&g_cursor[d1], 1);
        g_col[p1] = s1;
    } else {
        if (i >= E) return;
        int src = eidx(ei, i, is64);
        int dst = eidx(ei, (long long)E + i, is64);
        int pos = atomicAdd(&g_cursor[dst], 1);
        g_col[pos] = src;
    }
}

// ------------- mean aggregation (fp16 gather, fp32 accumulate) -------------
// PERMANENTLY FROZEN R5/R8 structure — DO NOT MODIFY (5 attempts regressed).
__global__ void k_agg(const __half* __restrict__ hin, __half* __restrict__ out, int N) {
    int node = (blockIdx.x * blockDim.x + threadIdx.x) >> 5;
    int lane = threadIdx.x & 31;
    if (node >= N) return;
    int beg = g_rowptr[node];
    int end = g_rowptr[node + 1];
    const uint2* hp = (const uint2*)hin;   // 32 uint2 per row
    float a0 = 0.f, a1 = 0.f, a2 = 0.f, a3 = 0.f;
    float b0 = 0.f, b1 = 0.f, b2 = 0.f, b3 = 0.f;
    int j = beg;
    for (; j + 3 < end; j += 4) {
        int s0 = __ldg(&g_col[j]);
        int s1 = __ldg(&g_col[j + 1]);
        int s2 = __ldg(&g_col[j + 2]);
        int s3 = __ldg(&g_col[j + 3]);
        uint2 u0 = __ldg(&hp[(long long)s0 * 32 + lane]);
        uint2 u1 = __ldg(&hp[(long long)s1 * 32 + lane]);
        uint2 u2 = __ldg(&hp[(long long)s2 * 32 + lane]);
        uint2 u3 = __ldg(&hp[(long long)s3 * 32 + lane]);
        float2 p0 = __half22float2(*(__half2*)&u0.x);
        float2 p1 = __half22float2(*(__half2*)&u0.y);
        float2 q0 = __half22float2(*(__half2*)&u1.x);
        float2 q1 = __half22float2(*(__half2*)&u1.y);
        float2 r0 = __half22float2(*(__half2*)&u2.x);
        float2 r1 = __half22float2(*(__half2*)&u2.y);
        float2 t0 = __half22float2(*(__half2*)&u3.x);
        float2 t1 = __half22float2(*(__half2*)&u3.y);
        a0 += p0.x + r0.x; a1 += p0.y + r0.y; a2 += p1.x + r1.x; a3 += p1.y + r1.y;
        b0 += q0.x + t0.x; b1 += q0.y + t0.y; b2 += q1.x + t1.x; b3 += q1.y + t1.y;
    }
    for (; j < end; j++) {
        int s = __ldg(&g_col[j]);
        uint2 u = __ldg(&hp[(long long)s * 32 + lane]);
        float2 p0 = __half22float2(*(__half2*)&u.x);
        float2 p1 = __half22float2(*(__half2*)&u.y);
        a0 += p0.x; a1 += p0.y; a2 += p1.x; a3 += p1.y;
    }
    float dv = g_dinv[node];
    float m0 = (a0 + b0) * dv, m1 = (a1 + b1) * dv;
    float m2 = (a2 + b2) * dv, m3 = (a3 + b3) * dv;
    __half2 o01 = __floats2half2_rn(m0, m1);
    __half2 o23 = __floats2half2_rn(m2, m3);
    uint2 ov;
    ov.x = *(uint32_t*)&o01;
    ov.y = *(uint32_t*)&o23;
    ((uint2*)out)[(long long)node * 32 + lane] = ov;
}

// ------------------- tf32 tensor-core fused SAGE GEMM ----------------------
__global__ void __launch_bounds__(256, 2)
k_gemm(const __half* __restrict__ A, const __half* __restrict__ X,
       const unsigned long long* __restrict__ wA,
       const unsigned long long* __restrict__ wX,
       const float* __restrict__ bias,
       __half* __restrict__ outH, int N, int leaky) {
    __shared__ uint32_t sA[8192];   // [sidx(8)][mb(8)][lane(32)][reg(4)]
    int tid = threadIdx.x;
    int lane = tid & 31;
    int wid = tid >> 5;
    int warp_n = wid & 1;
    int warp_m = wid >> 1;
    long long row0 = (long long)blockIdx.x * 128;

    float acc[2][8][4];
#pragma unroll
    for (int mi = 0; mi < 2; mi++)
#pragma unroll
        for (int ni = 0; ni < 8; ni++)
#pragma unroll
            for (int r = 0; r < 4; r++) acc[mi][ni][r] = 0.f;

#pragma unroll 1
    for (int seg = 0; seg < 2; seg++) {
        const __half* src = seg ? X : A;
        const unsigned long long* gw = seg ? wX : wA;
#pragma unroll 1
        for (int p = 0; p < 2; p++) {
            __syncthreads();
#pragma unroll
            for (int it = 0; it < 8; it++) {
                int i = tid + it * 256;        // 2048 uint2 slots (4 halves)
                int r = i >> 4, kq = i & 15;
                long long grow = row0 + r;
                uint2 v = make_uint2(0, 0);
                if (grow < N)
                    v = __ldg((const uint2*)src + grow * 32 + p * 16 + kq);
                float2 f01 = __half22float2(*(__half2*)&v.x);
                float2 f23 = __half22float2(*(__half2*)&v.y);
                int k0 = kq * 4;
                int g = r & 15, mb = r >> 4;
                int sidx = k0 >> 3;
                int reg = ((g >> 3) & 1) | (((k0 & 7) >> 2) << 1);
                uint32_t base = (((sidx * 8 + mb) * 32 + ((g & 7) << 2)) << 2) + reg;
                sA[base]      = f2tf32(f01.x);
                sA[base + 4]  = f2tf32(f01.y);
                sA[base + 8]  = f2tf32(f23.x);
                sA[base + 12] = f2tf32(f23.y);
            }
            __syncthreads();
#pragma unroll
            for (int s = 0; s < 8; s++) {
                uint4 a0 = *(const uint4*)&sA[((s * 8 + warp_m * 2 + 0) * 32 + lane) * 4];
                uint4 a1 = *(const uint4*)&sA[((s * 8 + warp_m * 2 + 1) * 32 + lane) * 4];
                unsigned long long bv[8];
#pragma unroll
                for (int nb = 0; nb < 8; nb++)
                    bv[nb] = __ldg(gw + (((p * 8 + s) * 16 + warp_n * 8 + nb) * 32 + lane));
#pragma unroll
                for (int nb = 0; nb < 8; nb++) {
                    MMA_TF32(acc[0][nb], a0, bv[nb]);
                    MMA_TF32(acc[1][nb], a1, bv[nb]);
                }
            }
        }
    }

    int g4 = lane >> 2, t4 = lane & 3;
#pragma unroll
    for (int mi = 0; mi < 2; mi++) {
#pragma unroll
        for (int ni = 0; ni < 8; ni++) {
            int col = warp_n * 64 + ni * 8 + t4 * 2;
            float b0 = __ldg(bias + col);
            float b1 = __ldg(bias + col + 1);
            long long r0 = row0 + warp_m * 32 + mi * 16 + g4;
            float v0 = acc[mi][ni][0] + b0;
            float v1 = acc[mi][ni][1] + b1;
            float v2 = acc[mi][ni][2] + b0;
            float v3 = acc[mi][ni][3] + b1;
            if (leaky) {
                v0 = v0 >= 0.f ? v0 : 0.2f * v0;
                v1 = v1 >= 0.f ? v1 : 0.2f * v1;
                v2 = v2 >= 0.f ? v2 : 0.2f * v2;
                v3 = v3 >= 0.f ? v3 : 0.2f * v3;
            }
            if (r0 < N) {
                __half2 o = __floats2half2_rn(v0, v1);
                *(uint32_t*)(outH + r0 * 128 + col) = *(uint32_t*)&o;
            }
            if (r0 + 8 < N) {
                __half2 o = __floats2half2_rn(v2, v3);
                *(uint32_t*)(outH + (r0 + 8) * 128 + col) = *(uint32_t*)&o;
            }
        }
    }
}

// ------------------- link prediction dot (fp16, 2 edges per warp) -----------
// Half-warp per edge: 16 lanes x uint4 = one 256B row per LDG half.
__global__ void k_dot(const __half* __restrict__ h, const void* __restrict__ eli,
                      float* __restrict__ out, int L) {
    int gwarp = (blockIdx.x * blockDim.x + threadIdx.x) >> 5;
    int lane = threadIdx.x & 31;
    int sub = lane >> 4;
    int fl  = lane & 15;
    int edge = gwarp * 2 + sub;
    if (edge >= L) return;
    int is64 = g_is64;
    int a = eidx(eli, edge, is64);
    int b = eidx(eli, (long long)L + edge, is64);
    const uint4* hp = (const uint4*)h;   // 16 uint4 per 128-half row
    uint4 ua = __ldg(&hp[(long long)a * 16 + fl]);
    uint4 ub = __ldg(&hp[(long long)b * 16 + fl]);
    float s = 0.f;
    float2 pa, pb;
    pa = __half22float2(*(__half2*)&ua.x); pb = __half22float2(*(__half2*)&ub.x);
    s += pa.x * pb.x + pa.y * pb.y;
    pa = __half22float2(*(__half2*)&ua.y); pb = __half22float2(*(__half2*)&ub.y);
    s += pa.x * pb.x + pa.y * pb.y;
    pa = __half22float2(*(__half2*)&ua.z); pb = __half22float2(*(__half2*)&ub.z);
    s += pa.x * pb.x + pa.y * pb.y;
    pa = __half22float2(*(__half2*)&ua.w); pb = __half22float2(*(__half2*)&ub.w);
    s += pa.x * pb.x + pa.y * pb.y;
#pragma unroll
    for (int o = 8; o; o >>= 1) s += __shfl_xor_sync(0xFFFFFFFFu, s, o);
    if (fl == 0) out[edge] = s;
}

extern "C" void kernel_launch(void* const* d_in, const int* in_sizes, int n_in,
                              void* d_out, int out_size) {
    const float* x   = (const float*)d_in[0];
    const void*  ei  = d_in[1];
    const void*  eli = d_in[2];
    const float* W1l = (const float*)d_in[3];
    const float* b1  = (const float*)d_in[4];
    const float* W1r = (const float*)d_in[5];
    const float* W2l = (const float*)d_in[6];
    const float* b2  = (const float*)d_in[7];
    const float* W2r = (const float*)d_in[8];
    float* out = (float*)d_out;

    int N = in_sizes[0] / 128;
    int E = in_sizes[1] / 2;
    int L = in_sizes[2] / 2;

    __half *xh, *aggh, *h1h, *h2h;
    uint32_t* wtf;
    cudaGetSymbolAddress((void**)&xh,   g_xh);
    cudaGetSymbolAddress((void**)&aggh, g_aggh);
    cudaGetSymbolAddress((void**)&h1h,  g_h1h);
    cudaGetSymbolAddress((void**)&h2h,  g_h2h);
    cudaGetSymbolAddress((void**)&wtf,  g_wtf);

    // CSR build + prep
    k_init<<<(N + 255) / 256, 256>>>(ei, E, N);
    int cntThreads = (E & 1) ? E : E / 2;
    k_count<<<(cntThreads + 255) / 256, 256>>>(ei, E);
    int nb = (N + 2047) / 2048;
    k_scan1<<<nb, 256>>>(N);
    k_scan2<<<1, 64>>>(nb, N);
    int ba = (N + 255) / 256;
    int bc = (N * 16 + 255) / 256;
    k_prep<<<ba + 256 + bc, 256>>>(N, ba, W1l, W1r, W2l, W2r, x, xh);
    k_fill<<<(cntThreads + 255) / 256, 256>>>(ei, E);

    const unsigned long long* w1l = (const unsigned long long*)(wtf + 0 * 16384);
    const unsigned long long* w1r = (const unsigned long long*)(wtf + 1 * 16384);
    const unsigned long long* w2l = (const unsigned long long*)(wtf + 2 * 16384);
    const unsigned long long* w2r = (const unsigned long long*)(wtf + 3 * 16384);

    int aggBlocks = (N + 7) / 8;
    int gemmBlocks = (N + 127) / 128;

    // Layer 1
    k_agg<<<aggBlocks, 256>>>(xh, aggh, N);
    k_gemm<<<gemmBlocks, 256>>>(aggh, xh, w1l, w1r, b1, h1h, N, 1);
    // Layer 2
    k_agg<<<aggBlocks, 256>>>(h1h, aggh, N);
    k_gemm<<<gemmBlocks, 256>>>(aggh, h1h, w2l, w2r, b2, h2h, N, 0);
    // Edge dot (2 edges per warp)
    int dotWarps = (L + 1) / 2;
    k_dot<<<(dotWarps + 7) / 8, 256>>>(h2h, eli, out, L);
}